// round 1
// baseline (speedup 1.0000x reference)
#include <cuda_runtime.h>

#define T_DIM   2000
#define KFR     400
#define KD      400
#define A_DIM   100
#define TSPLIT  5
#define TCHUNK  (T_DIM / TSPLIT)
#define EPSF    1e-24f

// Scratch (no allocations allowed) — re-zeroed at the start of every launch.
__device__ float d_gll[KFR * A_DIM];   // g_ll[k, a]
__device__ float d_ll[KFR];            // ll[k]

__global__ void mmdglm_zero() {
    int i = blockIdx.x * blockDim.x + threadIdx.x;
    if (i < KFR * A_DIM) d_gll[i] = 0.0f;
    if (i < KFR)         d_ll[i]  = 0.0f;
}

// One warp per (t,k) row: lanes 0..24 hold float4 chunks of X_fr[t,k,:] (A=100).
// Fused: u = x.theta -> r = exp(u) -> per-row weight w -> g_ll accumulation,
// so X_fr is read exactly once (320 MB total).
__global__ __launch_bounds__(128) void mmdglm_main(
    const float* __restrict__ tg, const int* __restrict__ mask,
    const float* __restrict__ X, const float* __restrict__ theta)
{
    const int k     = blockIdx.y;
    const int split = blockIdx.x;
    const int warp  = threadIdx.x >> 5;
    const int lane  = threadIdx.x & 31;
    const float dt  = tg[1] - tg[0];

    float4 th = make_float4(0.f, 0.f, 0.f, 0.f);
    if (lane < 25) th = __ldg(((const float4*)theta) + lane);

    float g0 = 0.f, g1 = 0.f, g2 = 0.f, g3 = 0.f, llacc = 0.f;

    const int tbeg = split * TCHUNK + warp;
    const int tend = split * TCHUNK + TCHUNK;
    const float4* xrow = (const float4*)(X + ((size_t)tbeg * KFR + k) * A_DIM);
    const size_t rowstride4 = (size_t)4 * KFR * A_DIM / 4;   // t += 4 in float4 units

    #pragma unroll 2
    for (int tt = tbeg; tt < tend; tt += 4, xrow += rowstride4) {
        float4 x = make_float4(0.f, 0.f, 0.f, 0.f);
        if (lane < 25) x = __ldg(xrow + lane);

        float p = x.x * th.x + x.y * th.y + x.z * th.z + x.w * th.w;
        #pragma unroll
        for (int o = 16; o; o >>= 1) p += __shfl_xor_sync(0xffffffffu, p, o);

        const float r   = __expf(p);      // non_linearity = exp
        const float dtr = dt * r;
        const int   m   = __ldg(mask + (size_t)tt * KFR + k);

        float w, llc;
        if (m) {
            const float e  = __expf(dtr);
            const float em = __expf(-dtr);
            w   = __fdividef(dtr, e - 1.0f - EPSF);
            llc = __logf(1.0f - em + EPSF);
        } else {
            w   = -dtr;
            llc = -dtr;
        }

        g0 += w * x.x; g1 += w * x.y; g2 += w * x.z; g3 += w * x.w;
        if (lane == 0) llacc += llc;
    }

    if (lane < 25) {
        float* dst = d_gll + k * A_DIM + lane * 4;
        atomicAdd(dst + 0, g0); atomicAdd(dst + 1, g1);
        atomicAdd(dst + 2, g2); atomicAdd(dst + 3, g3);
    }
    if (lane == 0) atomicAdd(d_ll + k, llacc);
}

// Everything downstream is rank-1 in phi, so it collapses to 6 scalars + two
// 100-vectors (Ga, Ha). Single block.
__global__ __launch_bounds__(128) void mmdglm_finalize(
    const float* __restrict__ phi_d, const float* __restrict__ phi_fr,
    float* __restrict__ out)
{
    __shared__ float shp[4][6];
    __shared__ float sc[6];
    const int tid = threadIdx.x, lane = tid & 31, warp = tid >> 5;

    float a0 = 0.f, a1 = 0.f, a2 = 0.f, a3 = 0.f, a4 = 0.f, a5 = 0.f;
    for (int i = tid; i < KFR; i += 128) {
        const float pf = phi_fr[i], pd = phi_d[i], l = d_ll[i];
        a0 += pf;      a1 += pf * pf;
        a2 += pd;      a3 += pd * pd;
        a4 += l * pf;  a5 += l * pf * pf;
    }
    #pragma unroll
    for (int o = 16; o; o >>= 1) {
        a0 += __shfl_xor_sync(0xffffffffu, a0, o);
        a1 += __shfl_xor_sync(0xffffffffu, a1, o);
        a2 += __shfl_xor_sync(0xffffffffu, a2, o);
        a3 += __shfl_xor_sync(0xffffffffu, a3, o);
        a4 += __shfl_xor_sync(0xffffffffu, a4, o);
        a5 += __shfl_xor_sync(0xffffffffu, a5, o);
    }
    if (lane == 0) {
        shp[warp][0] = a0; shp[warp][1] = a1; shp[warp][2] = a2;
        shp[warp][3] = a3; shp[warp][4] = a4; shp[warp][5] = a5;
    }
    __syncthreads();
    if (tid < 6) sc[tid] = shp[0][tid] + shp[1][tid] + shp[2][tid] + shp[3][tid];
    __syncthreads();

    const float S_fr = sc[0], Q_fr = sc[1], S_d = sc[2], Q_d = sc[3];
    const float P1 = sc[4], P2 = sc[5];
    const float n_fr = 0.5f * (float)KFR * (float)(KFR - 1);
    const float n_d  = 0.5f * (float)KD  * (float)(KD - 1);
    const float inv_kdkfr = 1.0f / ((float)KD * (float)KFR);

    if (tid == 0) {
        // mmd_grad
        out[0] = (P1 * S_fr - P2) / n_fr - 2.0f * S_d * P1 * inv_kdkfr;
        // mmd (unbiased off-diagonal means)
        out[1 + A_DIM] = (S_d * S_d - Q_d) / (2.0f * n_d)
                       + (S_fr * S_fr - Q_fr) / (2.0f * n_fr)
                       - 2.0f * S_d * S_fr * inv_kdkfr;
    }

    if (tid < A_DIM) {
        float Ga = 0.f, Ha = 0.f;
        for (int i = 0; i < KFR; i++) {
            const float g  = d_gll[i * A_DIM + tid];
            const float pf = phi_fr[i];
            Ga += pf * g;
            Ha += pf * pf * g;
        }
        out[1 + tid] = (S_fr * Ga - Ha) / n_fr - 2.0f * S_d * Ga * inv_kdkfr;
    }
}

extern "C" void kernel_launch(void* const* d_in, const int* in_sizes, int n_in,
                              void* d_out, int out_size) {
    const float* t      = (const float*)d_in[0];
    const int*   mask   = (const int*)  d_in[1];
    const float* X      = (const float*)d_in[2];
    const float* theta  = (const float*)d_in[3];
    const float* phi_d  = (const float*)d_in[4];
    const float* phi_fr = (const float*)d_in[5];
    float* out = (float*)d_out;

    mmdglm_zero<<<(KFR * A_DIM + 255) / 256, 256>>>();

    dim3 grid(TSPLIT, KFR);
    mmdglm_main<<<grid, 128>>>(t, mask, X, theta);

    mmdglm_finalize<<<1, 128>>>(phi_d, phi_fr, out);
}